// round 2
// baseline (speedup 1.0000x reference)
#include <cuda_runtime.h>
#include <cstdint>
#include <cstddef>

// Problem constants (fixed by the reference)
#define D_   256
#define NQ_  1024     // B * Q_PER_IMAGE
#define B_   4
#define NF_  65536    // feats per image

// Scratch for MLP ping-pong (allocations are forbidden; __device__ globals are the sanctioned path)
__device__ float g_buf1[NQ_ * D_];
__device__ float g_buf2[NQ_ * D_];

// ---------------------------------------------------------------------------
// MLP layer: Y[m][n] = act( sum_k X[m][k] * W[n][k] + bias[n] )
// X: [1024, 256], W: [256, 256] (torch Linear: [out, in]), Y: [1024, 256]
// 64x64 block tile, 256 threads, 4x4 register tile, k-major (transposed) smem
// ---------------------------------------------------------------------------
__global__ __launch_bounds__(256) void mlp_layer(
    const float* __restrict__ X, const float* __restrict__ W,
    const float* __restrict__ bias, float* __restrict__ Y, int do_relu)
{
    __shared__ __align__(16) float Xs[32][68];  // [k][m], padded
    __shared__ __align__(16) float Ws[32][68];  // [k][n], padded

    const int n0 = blockIdx.x * 64;
    const int m0 = blockIdx.y * 64;
    const int tid = threadIdx.x;
    const int tx = tid & 15;       // n sub-tile
    const int ty = tid >> 4;       // m sub-tile
    const int lr = tid >> 3;       // load row (0..31)
    const int lc = (tid & 7) * 4;  // load col (float4)

    float acc[4][4];
#pragma unroll
    for (int i = 0; i < 4; i++)
#pragma unroll
        for (int j = 0; j < 4; j++) acc[i][j] = 0.f;

    for (int k0 = 0; k0 < D_; k0 += 32) {
#pragma unroll
        for (int p = 0; p < 2; p++) {
            int r = lr + p * 32;
            float4 xv = *reinterpret_cast<const float4*>(&X[(size_t)(m0 + r) * D_ + k0 + lc]);
            Xs[lc + 0][r] = xv.x; Xs[lc + 1][r] = xv.y;
            Xs[lc + 2][r] = xv.z; Xs[lc + 3][r] = xv.w;
            float4 wv = *reinterpret_cast<const float4*>(&W[(size_t)(n0 + r) * D_ + k0 + lc]);
            Ws[lc + 0][r] = wv.x; Ws[lc + 1][r] = wv.y;
            Ws[lc + 2][r] = wv.z; Ws[lc + 3][r] = wv.w;
        }
        __syncthreads();
#pragma unroll
        for (int kk = 0; kk < 32; kk++) {
            float4 xa = *reinterpret_cast<const float4*>(&Xs[kk][ty * 4]);
            float4 wb = *reinterpret_cast<const float4*>(&Ws[kk][tx * 4]);
            float xs[4] = {xa.x, xa.y, xa.z, xa.w};
            float ws[4] = {wb.x, wb.y, wb.z, wb.w};
#pragma unroll
            for (int i = 0; i < 4; i++)
#pragma unroll
                for (int j = 0; j < 4; j++) acc[i][j] += xs[i] * ws[j];
        }
        __syncthreads();
    }

#pragma unroll
    for (int i = 0; i < 4; i++) {
        float4 o;
        float* po = &o.x;
#pragma unroll
        for (int j = 0; j < 4; j++) {
            float v = acc[i][j] + bias[n0 + tx * 4 + j];
            if (do_relu) v = fmaxf(v, 0.f);
            po[j] = v;
        }
        *reinterpret_cast<float4*>(&Y[(size_t)(m0 + ty * 4 + i) * D_ + n0 + tx * 4]) = o;
    }
}

// ---------------------------------------------------------------------------
// Logits GEMM (per batch): out[b][n][q] = sum_k feats[b*NF+n][k] * Xq[b*256+q][k]
// tf32 mma.sync m16n8k8, 128x128x16 block tile, cp.async double buffer,
// 8 warps laid out 4(m) x 2(n), each warp 32x64 (2 m-tiles x 8 n-tiles).
// ---------------------------------------------------------------------------
#define BM 128
#define BN 128
#define BK 16
#define KSTEPS (D_ / BK)   // 16

__device__ __forceinline__ uint32_t f2tf32(float x) {
    uint32_t r;
    asm("cvt.rna.tf32.f32 %0, %1;" : "=r"(r) : "f"(x));
    return r;
}

__device__ __forceinline__ void mma_tf32(float c[4], const uint32_t a[4], const uint32_t b[2]) {
    asm volatile(
        "mma.sync.aligned.m16n8k8.row.col.f32.tf32.tf32.f32 "
        "{%0,%1,%2,%3},{%4,%5,%6,%7},{%8,%9},{%0,%1,%2,%3};"
        : "+f"(c[0]), "+f"(c[1]), "+f"(c[2]), "+f"(c[3])
        : "r"(a[0]), "r"(a[1]), "r"(a[2]), "r"(a[3]), "r"(b[0]), "r"(b[1]));
}

__global__ __launch_bounds__(256) void logits_gemm(
    const float* __restrict__ F, const float* __restrict__ Q, float* __restrict__ out)
{
    __shared__ __align__(16) float As[2][BM][BK + 4];
    __shared__ __align__(16) float Bs[2][BN][BK + 4];

    const int nb = blockIdx.x;   // 0..1  (n-inner: the two N-blocks sharing an A tile co-schedule -> L2 reuse)
    const int mb = blockIdx.y;   // 0..511
    const int b  = blockIdx.z;   // 0..3

    const float* Ab = F + ((size_t)b * NF_ + (size_t)mb * BM) * D_;
    const float* Bb = Q + ((size_t)b * 256 + (size_t)nb * BN) * D_;

    const int tid = threadIdx.x;
    const int ldr = tid >> 2;          // 0..63
    const int ldc = (tid & 3) * 4;     // 0,4,8,12 floats (16B chunk)

    const int w = tid >> 5, lane = tid & 31;
    const int wm = (w & 3) * 32;       // warp m origin in tile
    const int wn = (w >> 2) * 64;      // warp n origin in tile
    const int g = lane >> 2, t = lane & 3;

    float acc[2][8][4];
#pragma unroll
    for (int mt = 0; mt < 2; mt++)
#pragma unroll
        for (int nt = 0; nt < 8; nt++)
#pragma unroll
            for (int i = 0; i < 4; i++) acc[mt][nt][i] = 0.f;

    auto issue = [&](int kt, int buf) {
        const int k0 = kt * BK;
#pragma unroll
        for (int p = 0; p < 2; p++) {
            int r = ldr + p * 64;
            uint32_t sa = (uint32_t)__cvta_generic_to_shared(&As[buf][r][ldc]);
            const float* ga = Ab + (size_t)r * D_ + k0 + ldc;
            asm volatile("cp.async.cg.shared.global [%0], [%1], 16;" :: "r"(sa), "l"(ga));
            uint32_t sb = (uint32_t)__cvta_generic_to_shared(&Bs[buf][r][ldc]);
            const float* gb = Bb + (size_t)r * D_ + k0 + ldc;
            asm volatile("cp.async.cg.shared.global [%0], [%1], 16;" :: "r"(sb), "l"(gb));
        }
    };

    issue(0, 0);
    asm volatile("cp.async.commit_group;");

    for (int kt = 0; kt < KSTEPS; kt++) {
        const int buf = kt & 1;
        if (kt + 1 < KSTEPS) issue(kt + 1, buf ^ 1);
        asm volatile("cp.async.commit_group;");
        asm volatile("cp.async.wait_group 1;");
        __syncthreads();

#pragma unroll
        for (int ks = 0; ks < BK; ks += 8) {
            uint32_t a[2][4];
#pragma unroll
            for (int mt = 0; mt < 2; mt++) {
                int r = wm + mt * 16;
                a[mt][0] = f2tf32(As[buf][r + g    ][ks + t    ]);
                a[mt][1] = f2tf32(As[buf][r + g + 8][ks + t    ]);
                a[mt][2] = f2tf32(As[buf][r + g    ][ks + t + 4]);
                a[mt][3] = f2tf32(As[buf][r + g + 8][ks + t + 4]);
            }
            uint32_t bf[8][2];
#pragma unroll
            for (int nt = 0; nt < 8; nt++) {
                int c = wn + nt * 8;
                bf[nt][0] = f2tf32(Bs[buf][c + g][ks + t    ]);
                bf[nt][1] = f2tf32(Bs[buf][c + g][ks + t + 4]);
            }
#pragma unroll
            for (int mt = 0; mt < 2; mt++)
#pragma unroll
                for (int nt = 0; nt < 8; nt++)
                    mma_tf32(acc[mt][nt], a[mt], bf[nt]);
        }
        __syncthreads();
    }

    // Epilogue: out row = feature index, col = query index (width 256)
    const size_t orow0 = (size_t)b * NF_ + (size_t)mb * BM + wm;
    const int col0 = nb * BN + wn;
#pragma unroll
    for (int mt = 0; mt < 2; mt++) {
#pragma unroll
        for (int nt = 0; nt < 8; nt++) {
            size_t r0 = orow0 + mt * 16 + g;
            int c = col0 + nt * 8 + 2 * t;
            float2 v0 = make_float2(acc[mt][nt][0], acc[mt][nt][1]);
            float2 v1 = make_float2(acc[mt][nt][2], acc[mt][nt][3]);
            *reinterpret_cast<float2*>(&out[r0 * 256 + c]) = v0;
            *reinterpret_cast<float2*>(&out[(r0 + 8) * 256 + c]) = v1;
        }
    }
}

// ---------------------------------------------------------------------------
// Launch. Input order (metadata): queries, feature_values, feature_indices,
// query_batch_offsets, W1, b1, W2, b2, W3, b3, W4, b4.
// feature_indices / query_batch_offsets are not needed for the output values.
// ---------------------------------------------------------------------------
extern "C" void kernel_launch(void* const* d_in, const int* in_sizes, int n_in,
                              void* d_out, int out_size)
{
    (void)in_sizes; (void)n_in; (void)out_size;
    const float* queries = (const float*)d_in[0];
    const float* feats   = (const float*)d_in[1];
    const float* W1 = (const float*)d_in[4];
    const float* b1 = (const float*)d_in[5];
    const float* W2 = (const float*)d_in[6];
    const float* b2 = (const float*)d_in[7];
    const float* W3 = (const float*)d_in[8];
    const float* b3 = (const float*)d_in[9];
    const float* W4 = (const float*)d_in[10];
    const float* b4 = (const float*)d_in[11];
    float* out = (float*)d_out;

    float *p1 = nullptr, *p2 = nullptr;
    cudaGetSymbolAddress((void**)&p1, g_buf1);
    cudaGetSymbolAddress((void**)&p2, g_buf2);

    dim3 mg(D_ / 64, NQ_ / 64);  // (4, 16)
    mlp_layer<<<mg, 256>>>(queries, W1, b1, p1, 1);
    mlp_layer<<<mg, 256>>>(p1, W2, b2, p2, 1);
    mlp_layer<<<mg, 256>>>(p2, W3, b3, p1, 1);
    mlp_layer<<<mg, 256>>>(p1, W4, b4, p2, 0);

    logits_gemm<<<dim3(2, NF_ / BM, B_), 256>>>(feats, p2, out);
}